// round 14
// baseline (speedup 1.0000x reference)
#include <cuda_runtime.h>
#include <cuda_fp16.h>
#include <cstdint>

#define SEQ  4096
#define DMODEL 1024
#define NH   16
#define HDIM 64
#define KSPLIT 2

// single fp16 A operand: X for QKV GEMM, then combined attention output for proj
__device__ __align__(16) __half g_x16[(long)SEQ * DMODEL];
// single fp16 weights, SAME layout as input: [K][N] (consumed k-major via ldsm.trans)
__device__ __align__(16) __half g_w1[(long)DMODEL * 3 * DMODEL];
__device__ __align__(16) __half g_w2[(long)DMODEL * DMODEL];
// fp16 q/k/v (q pre-scaled by 0.125*log2e), head-major [h][seq][hd]
__device__ __align__(16) __half g_q16[(long)NH * SEQ * HDIM];
__device__ __align__(16) __half g_k16[(long)NH * SEQ * HDIM];
__device__ __align__(16) __half g_v16[(long)NH * SEQ * HDIM];
// split-KV partials: unnormalized O (fp16) + per-row m,l (fp32, exp2 domain)
__device__ __align__(16) __half g_opart[(long)KSPLIT * SEQ * DMODEL];
__device__ float g_pm[(long)KSPLIT * NH * SEQ];
__device__ float g_pl[(long)KSPLIT * NH * SEQ];
// per-(q-block, head) turnstile; zero-init, reset to zero by the combiner
__device__ int g_pflag[32 * NH];

#define QSCALE 0.18033688f   // 0.125 * log2(e)

// ---------------------------------------------------------------------------
__device__ __forceinline__ uint32_t smem_u32(const void* p) {
    uint32_t a;
    asm("{ .reg .u64 t; cvta.to.shared.u64 t, %1; cvt.u32.u64 %0, t; }" : "=r"(a) : "l"(p));
    return a;
}
__device__ __forceinline__ float ex2(float x) {
    float y; asm("ex2.approx.f32 %0, %1;" : "=f"(y) : "f"(x)); return y;
}
#define CP16(dst, src) \
    asm volatile("cp.async.cg.shared.global [%0], [%1], 16;" :: "r"(dst), "l"(src))
#define CP_COMMIT() asm volatile("cp.async.commit_group;" ::: "memory")
#define CP_WAIT1()  asm volatile("cp.async.wait_group 1;" ::: "memory")
#define CP_WAIT0()  asm volatile("cp.async.wait_group 0;" ::: "memory")

#define LDSM4(r0, r1, r2, r3, addr) \
    asm volatile("ldmatrix.sync.aligned.m8n8.x4.shared.b16 {%0,%1,%2,%3}, [%4];" \
                 : "=r"(r0), "=r"(r1), "=r"(r2), "=r"(r3) : "r"(addr))
#define LDSM4T(r0, r1, r2, r3, addr) \
    asm volatile("ldmatrix.sync.aligned.m8n8.x4.trans.shared.b16 {%0,%1,%2,%3}, [%4];" \
                 : "=r"(r0), "=r"(r1), "=r"(r2), "=r"(r3) : "r"(addr))

#define MMAH(c, a, b0, b1) \
    asm volatile("mma.sync.aligned.m16n8k16.row.col.f32.f16.f16.f32 " \
                 "{%0,%1,%2,%3}, {%4,%5,%6,%7}, {%8,%9}, {%0,%1,%2,%3};" \
                 : "+f"((c)[0]), "+f"((c)[1]), "+f"((c)[2]), "+f"((c)[3]) \
                 : "r"((a)[0]), "r"((a)[1]), "r"((a)[2]), "r"((a)[3]), \
                   "r"(b0), "r"(b1))

__device__ __forceinline__ uint32_t h2u(__half2 h) { return *(uint32_t*)&h; }

// ---------------------------------------------------------------------------
// Fused conversion kernel: X -> g_x16, Wqkv -> g_w1, Wproj -> g_w2.
// ---------------------------------------------------------------------------
__global__ void conv_all_kernel(const float* __restrict__ X,
                                const float* __restrict__ W1,
                                const float* __restrict__ W2) {
    int b = blockIdx.x;
    const float* src;
    __half* dst;
    int j;
    if (b < 4096)      { src = X;  dst = g_x16; j = b * 256 + threadIdx.x; }
    else if (b < 7168) { src = W1; dst = g_w1;  j = (b - 4096) * 256 + threadIdx.x; }
    else               { src = W2; dst = g_w2;  j = (b - 7168) * 256 + threadIdx.x; }
    float4 v = ((const float4*)src)[j];
    __half2* H = (__half2*)dst;
    H[2*j]   = __floats2half2_rn(v.x, v.y);
    H[2*j+1] = __floats2half2_rn(v.z, v.w);
}

// ---------------------------------------------------------------------------
// Single-fp16 GEMM, 128 threads / 4 warps, warp tile 64x64 (round-12 config).
// ---------------------------------------------------------------------------
template <int MODE>
__global__ __launch_bounds__(128, 2) void gemm16(
    const float* __restrict__ bias, float* __restrict__ C, int N)
{
    const __half* __restrict__ B = MODE ? g_w1 : g_w2;
    const int K = DMODEL;
    extern __shared__ char smem[];
    const uint32_t sb = smem_u32(smem);
    const int tid  = threadIdx.x;
    const int lane = tid & 31;
    const int wid  = tid >> 5;
    const int wm   = wid >> 1;
    const int wn   = wid & 1;
    const int n0 = blockIdx.x * 128, m0 = blockIdx.y * 128;

    float acc[4][8][4];
#pragma unroll
    for (int mt = 0; mt < 4; mt++)
#pragma unroll
        for (int nt = 0; nt < 8; nt++)
#pragma unroll
            for (int r = 0; r < 4; r++) acc[mt][nt][r] = 0.f;

    auto load_stage = [&](int stg, int ck) {
        const uint32_t st = sb + (uint32_t)stg * 32768;
        const int k0 = ck * 64;
#pragma unroll
        for (int it = 0; it < 8; it++) {
            int id  = it * 128 + tid;
            int row = id >> 3, kc = id & 7;
            const void* g = g_x16 + (size_t)(m0 + row) * K + k0 + kc * 8;
            uint32_t soff = (uint32_t)(row * 128 + ((kc * 16) ^ ((row & 7) << 4)));
            CP16(st + soff, g);
        }
#pragma unroll
        for (int it = 0; it < 8; it++) {
            int id  = it * 128 + tid;
            int row = id >> 4, c16 = id & 15;
            const void* g = B + (size_t)(k0 + row) * N + n0 + c16 * 8;
            uint32_t soff = (uint32_t)(row * 256 + ((c16 * 16) ^ ((row & 15) << 4)));
            CP16(st + 16384 + soff, g);
        }
    };

    const int NC = K / 64;
    load_stage(0, 0); CP_COMMIT();
    load_stage(1, 1); CP_COMMIT();

    const int r_lane = lane & 15;
    const int c_lane = (lane >> 4) << 4;
    const uint32_t xorA = (uint32_t)((r_lane & 7) << 4);
    const uint32_t xorB = (uint32_t)(r_lane << 4);
    const uint32_t colB = (uint32_t)(wn * 128 + c_lane);

    for (int c = 0; c < NC; c++) {
        if (c + 1 < NC) { CP_WAIT1(); } else { CP_WAIT0(); }
        __syncthreads();
        if (c + 2 < NC) { load_stage((c + 2) % 3, c + 2); CP_COMMIT(); }

        const uint32_t st = sb + (uint32_t)(c % 3) * 32768;
        const uint32_t aA = st +         (uint32_t)((wm * 64 + r_lane) * 128);
        const uint32_t rB = st + 16384 + (uint32_t)(r_lane * 256);

#pragma unroll
        for (int ks = 0; ks < 4; ks++) {
            const uint32_t cvA = ((uint32_t)(ks * 32 + c_lane)) ^ xorA;
            uint32_t ah[4][4], bh[4][4];
#pragma unroll
            for (int mt = 0; mt < 4; mt++)
                LDSM4(ah[mt][0], ah[mt][1], ah[mt][2], ah[mt][3], aA + mt * 2048 + cvA);
#pragma unroll
            for (int bn = 0; bn < 4; bn++)
                LDSM4T(bh[bn][0], bh[bn][1], bh[bn][2], bh[bn][3],
                       rB + ks * 4096 + ((colB + bn * 32) ^ xorB));
#pragma unroll
            for (int mt = 0; mt < 4; mt++)
#pragma unroll
                for (int nt = 0; nt < 8; nt++) {
                    int bn = nt >> 1, sub = nt & 1;
                    MMAH(acc[mt][nt], ah[mt], bh[bn][sub * 2], bh[bn][sub * 2 + 1]);
                }
        }
    }

    const int rq = lane >> 2;
    const int cq = (lane & 3) * 2;
#pragma unroll
    for (int mt = 0; mt < 4; mt++) {
#pragma unroll
        for (int nt = 0; nt < 8; nt++) {
            int gcol = n0 + wn * 64 + nt * 8 + cq;
            float b0 = bias[gcol], b1 = bias[gcol + 1];
            if (MODE == 1) {
                int sect = gcol >> 10, w = gcol & 1023;
                int hh = w >> 6, dd = w & 63;
                __half* dst = (sect == 0) ? g_q16 : (sect == 1) ? g_k16 : g_v16;
                float sc = (sect == 0) ? QSCALE : 1.0f;
#pragma unroll
                for (int half = 0; half < 2; half++) {
                    int grow = m0 + wm * 64 + mt * 16 + rq + half * 8;
                    float vx = (acc[mt][nt][half * 2 + 0] + b0) * sc;
                    float vy = (acc[mt][nt][half * 2 + 1] + b1) * sc;
                    *(__half2*)&dst[((size_t)hh * SEQ + grow) * HDIM + dd] =
                        __floats2half2_rn(vx, vy);
                }
            } else {
#pragma unroll
                for (int half = 0; half < 2; half++) {
                    int grow = m0 + wm * 64 + mt * 16 + rq + half * 8;
                    float2 v;
                    v.x = acc[mt][nt][half * 2 + 0] + b0;
                    v.y = acc[mt][nt][half * 2 + 1] + b1;
                    *(float2*)&C[(size_t)grow * N + gcol] = v;
                }
            }
        }
    }
}

// ---------------------------------------------------------------------------
// FlashAttention-2, split-KV x2, 4 warps x 32 rows, fp16 partials. The SECOND
// split-CTA to finish each (iq,h) combines both partials inline (turnstile) —
// no separate combine kernel. Combine is a pure function of global data, so
// output is deterministic regardless of arrival order.
// ---------------------------------------------------------------------------
__global__ __launch_bounds__(128, 2) void attn_mma_kernel()
{
    extern __shared__ char smem[];
    const uint32_t sb = smem_u32(smem);
    const int tid = threadIdx.x, lane = tid & 31, wid = tid >> 5;
    const int sp = blockIdx.x;
    const int iq = 31 - (int)blockIdx.y;     // heavy blocks first
    const int h  = blockIdx.z;
    const int jbeg = sp * (iq + 1);
    const int jend = jbeg + iq + 1;

    const uint32_t Qs = sb;                  // 16KB

    auto load_kv = [&](int stg, int j) {
        const uint32_t st = sb + 16384 + (uint32_t)stg * 16384;
#pragma unroll
        for (int a = 0; a < 2; a++) {
            const __half* src = a ? g_v16 : g_k16;
#pragma unroll
            for (int it = 0; it < 4; it++) {
                int id = it * 128 + tid;
                int row = id >> 3, kc = id & 7;
                uint32_t soff = (uint32_t)(row * 128 + ((kc * 16) ^ ((row & 7) << 4)));
                CP16(st + a * 8192 + soff,
                     src + ((size_t)h * SEQ + j * 64 + row) * HDIM + kc * 8);
            }
        }
    };

    {
#pragma unroll
        for (int it = 0; it < 8; it++) {
            int id = it * 128 + tid;
            int row = id >> 3, kc = id & 7;
            uint32_t soff = (uint32_t)(row * 128 + ((kc * 16) ^ ((row & 7) << 4)));
            CP16(Qs + soff, g_q16 + ((size_t)h * SEQ + iq * 128 + row) * HDIM + kc * 8);
        }
        load_kv(0, jbeg);
        CP_COMMIT();
        if (jbeg + 1 < jend) { load_kv(1, jbeg + 1); CP_COMMIT(); }
    }

    float o[2][8][4];
#pragma unroll
    for (int mt = 0; mt < 2; mt++)
#pragma unroll
        for (int nt = 0; nt < 8; nt++)
#pragma unroll
            for (int r = 0; r < 4; r++) o[mt][nt][r] = 0.f;
    float mst[2][2], lst[2][2];
#pragma unroll
    for (int mt = 0; mt < 2; mt++) { mst[mt][0] = mst[mt][1] = -1e30f;
                                     lst[mt][0] = lst[mt][1] = 0.f; }
    uint32_t qf[2][4][4];

    const uint32_t xorterm = (uint32_t)((lane & 7) << 4);
    const uint32_t c_lane  = (uint32_t)((lane >> 4) << 4);
    int r0g[2];
#pragma unroll
    for (int mt = 0; mt < 2; mt++)
        r0g[mt] = iq * 128 + wid * 32 + mt * 16 + (lane >> 2);

    for (int j = jbeg; j < jend; j++) {
        const int jj = j - jbeg;
        if (j + 1 < jend) { CP_WAIT1(); } else { CP_WAIT0(); }
        __syncthreads();
        if (j + 2 < jend) { load_kv((jj + 2) % 3, j + 2); CP_COMMIT(); }

        if (jj == 0) {
#pragma unroll
            for (int mt = 0; mt < 2; mt++) {
                const uint32_t qrow = Qs +
                    (uint32_t)((wid * 32 + mt * 16 + (lane & 15)) * 128);
#pragma unroll
                for (int ks = 0; ks < 4; ks++) {
                    uint32_t cv = ((uint32_t)(ks * 32) + c_lane) ^ xorterm;
                    LDSM4(qf[mt][ks][0], qf[mt][ks][1], qf[mt][ks][2], qf[mt][ks][3],
                          qrow + cv);
                }
            }
        }

        const uint32_t st = sb + 16384 + (uint32_t)(jj % 3) * 16384;
        const uint32_t Ks = st, Vs = st + 8192;

        float s[2][8][4];
#pragma unroll
        for (int mt = 0; mt < 2; mt++)
#pragma unroll
            for (int nt = 0; nt < 8; nt++)
#pragma unroll
                for (int r = 0; r < 4; r++) s[mt][nt][r] = 0.f;

#pragma unroll
        for (int ks = 0; ks < 4; ks++) {
            uint32_t cv = ((uint32_t)(ks * 32) + c_lane) ^ xorterm;
#pragma unroll
            for (int bn = 0; bn < 4; bn++) {
                uint32_t kh[4];
                LDSM4(kh[0], kh[1], kh[2], kh[3],
                      Ks + (uint32_t)((bn * 16 + (lane & 15)) * 128) + cv);
#pragma unroll
                for (int mt = 0; mt < 2; mt++)
#pragma unroll
                    for (int sub = 0; sub < 2; sub++)
                        MMAH(s[mt][bn * 2 + sub], qf[mt][ks], kh[sub], kh[sub + 2]);
            }
        }

        if (j >= 2 * iq) {
            int cbase = j * 64 + (lane & 3) * 2;
#pragma unroll
            for (int mt = 0; mt < 2; mt++)
#pragma unroll
                for (int nt = 0; nt < 8; nt++) {
                    int c0 = cbase + nt * 8, c1 = c0 + 1;
                    if (c0 > r0g[mt])     s[mt][nt][0] = -1e30f;
                    if (c1 > r0g[mt])     s[mt][nt][1] = -1e30f;
                    if (c0 > r0g[mt] + 8) s[mt][nt][2] = -1e30f;
                    if (c1 > r0g[mt] + 8) s[mt][nt][3] = -1e30f;
                }
        }

#pragma unroll
        for (int mt = 0; mt < 2; mt++) {
            float mx0 = -1e30f, mx1 = -1e30f;
#pragma unroll
            for (int nt = 0; nt < 8; nt++) {
                mx0 = fmaxf(mx0, fmaxf(s[mt][nt][0], s[mt][nt][1]));
                mx1 = fmaxf(mx1, fmaxf(s[mt][nt][2], s[mt][nt][3]));
            }
            mx0 = fmaxf(mx0, __shfl_xor_sync(0xFFFFFFFFu, mx0, 1));
            mx0 = fmaxf(mx0, __shfl_xor_sync(0xFFFFFFFFu, mx0, 2));
            mx1 = fmaxf(mx1, __shfl_xor_sync(0xFFFFFFFFu, mx1, 1));
            mx1 = fmaxf(mx1, __shfl_xor_sync(0xFFFFFFFFu, mx1, 2));
            float mn0 = fmaxf(mst[mt][0], mx0), mn1 = fmaxf(mst[mt][1], mx1);
            float al0 = ex2(mst[mt][0] - mn0), al1 = ex2(mst[mt][1] - mn1);
            mst[mt][0] = mn0; mst[mt][1] = mn1;

            float sum0 = 0.f, sum1 = 0.f;
#pragma unroll
            for (int nt = 0; nt < 8; nt++) {
                s[mt][nt][0] = ex2(s[mt][nt][0] - mn0);
                s[mt][nt][1] = ex2(s[mt][nt][1] - mn0);
                s[mt][nt][2] = ex2(s[mt][nt][2] - mn1);
                s[mt][nt][3] = ex2(s[mt][nt][3] - mn1);
                sum0 += s[mt][nt][0] + s[mt][nt][1];
                sum1 += s[mt][nt][2] + s[mt][nt][3];
            }
            sum0 += __shfl_xor_sync(0xFFFFFFFFu, sum0, 1);
            sum0 += __shfl_xor_sync(0xFFFFFFFFu, sum0, 2);
            sum1 += __shfl_xor_sync(0xFFFFFFFFu, sum1, 1);
            sum1 += __shfl_xor_sync(0xFFFFFFFFu, sum1, 2);
            lst[mt][0] = lst[mt][0] * al0 + sum0;
            lst[mt][1] = lst[mt][1] * al1 + sum1;

#pragma unroll
            for (int nt = 0; nt < 8; nt++) {
                o[mt][nt][0] *= al0; o[mt][nt][1] *= al0;
                o[mt][nt][2] *= al1; o[mt][nt][3] *= al1;
            }
        }

#pragma unroll
        for (int t = 0; t < 4; t++) {
            uint32_t ap[2][4];
#pragma unroll
            for (int mt = 0; mt < 2; mt++)
#pragma unroll
                for (int u = 0; u < 4; u++) {
                    int nt = t * 2 + (u >> 1);
                    int base = (u & 1) * 2;
                    ap[mt][u] = h2u(__floats2half2_rn(s[mt][nt][base],
                                                      s[mt][nt][base + 1]));
                }
            uint32_t rowoff = (uint32_t)((t * 16 + (lane & 15)) * 128);
#pragma unroll
            for (int g = 0; g < 4; g++) {
                uint32_t cvv = ((uint32_t)(g * 32) + c_lane) ^ xorterm;
                uint32_t vh[4];
                LDSM4T(vh[0], vh[1], vh[2], vh[3], Vs + rowoff + cvv);
#pragma unroll
                for (int mt = 0; mt < 2; mt++) {
                    MMAH(o[mt][g * 2],     ap[mt], vh[0], vh[1]);
                    MMAH(o[mt][g * 2 + 1], ap[mt], vh[2], vh[3]);
                }
            }
        }
    }

    // ---- write unnormalized partials (fp16) + m,l ----
    __half* Op = g_opart + (size_t)sp * SEQ * DMODEL;
    int colb = h * 64 + (lane & 3) * 2;
#pragma unroll
    for (int mt = 0; mt < 2; mt++) {
#pragma unroll
        for (int nt = 0; nt < 8; nt++) {
            int col = colb + nt * 8;
            size_t i0 = (size_t)r0g[mt] * DMODEL + col;
            size_t i1 = (size_t)(r0g[mt] + 8) * DMODEL + col;
            *(__half2*)&Op[i0] = __floats2half2_rn(o[mt][nt][0], o[mt][nt][1]);
            *(__half2*)&Op[i1] = __floats2half2_rn(o[mt][nt][2], o[mt][nt][3]);
        }
        if ((lane & 3) == 0) {
            size_t base = (size_t)sp * NH * SEQ + (size_t)h * SEQ;
            g_pm[base + r0g[mt]]     = mst[mt][0];
            g_pm[base + r0g[mt] + 8] = mst[mt][1];
            g_pl[base + r0g[mt]]     = lst[mt][0];
            g_pl[base + r0g[mt] + 8] = lst[mt][1];
        }
    }

    // ---- turnstile: second arriver combines (deterministic: pure fn of gmem) ----
    __threadfence();
    __shared__ int s_old;
    __syncthreads();
    if (tid == 0) s_old = atomicAdd(&g_pflag[h * 32 + (int)blockIdx.y], 1);
    __syncthreads();
    if (s_old == 1) {
        __threadfence();
        const __half* P0 = g_opart;
        const __half* P1 = g_opart + (size_t)SEQ * DMODEL;
#pragma unroll
        for (int it = 0; it < 8; it++) {
            int r    = it * 16 + (tid >> 3);          // local row 0..127
            int cg   = (tid & 7) * 8;                 // col group (8 halves)
            int grow = iq * 128 + r;
            size_t mlb = (size_t)h * SEQ + grow;
            float m0 = g_pm[mlb], m1 = g_pm[(size_t)NH * SEQ + mlb];
            float l0 = g_pl[mlb], l1 = g_pl[(size_t)NH * SEQ + mlb];
            float ms = fmaxf(m0, m1);
            float w0 = ex2(m0 - ms), w1 = ex2(m1 - ms);
            float inv = 1.0f / (w0 * l0 + w1 * l1);
            w0 *= inv; w1 *= inv;
            size_t off = (size_t)grow * DMODEL + h * 64 + cg;
            uint4 ua = *(const uint4*)&P0[off];
            uint4 ub = *(const uint4*)&P1[off];
            uint4 uo;
            __half2* pa = (__half2*)&ua;
            __half2* pb = (__half2*)&ub;
            __half2* po = (__half2*)&uo;
#pragma unroll
            for (int q = 0; q < 4; q++) {
                float2 fa = __half22float2(pa[q]);
                float2 fb = __half22float2(pb[q]);
                po[q] = __floats2half2_rn(fa.x * w0 + fb.x * w1,
                                          fa.y * w0 + fb.y * w1);
            }
            *(uint4*)&g_x16[off] = uo;
        }
        __syncthreads();
        if (tid == 0) g_pflag[h * 32 + (int)blockIdx.y] = 0;   // replay-safe reset
    }
}

// ---------------------------------------------------------------------------
extern "C" void kernel_launch(void* const* d_in, const int* in_sizes, int n_in,
                              void* d_out, int out_size)
{
    const float* X     = (const float*)d_in[0];
    const float* Wqkv  = (const float*)d_in[1];
    const float* bqkv  = (const float*)d_in[2];
    const float* Wproj = (const float*)d_in[3];
    const float* bproj = (const float*)d_in[4];
    float* out = (float*)d_out;

    const int GEMM_SMEM = 3 * 2 * 16384;             // 98304 B, 2 CTAs/SM
    const int ATTN_SMEM = 16384 + 3 * 16384;         // 65536 B, 2 CTAs/SM
    cudaFuncSetAttribute(gemm16<1>, cudaFuncAttributeMaxDynamicSharedMemorySize, GEMM_SMEM);
    cudaFuncSetAttribute(gemm16<0>, cudaFuncAttributeMaxDynamicSharedMemorySize, GEMM_SMEM);
    cudaFuncSetAttribute(attn_mma_kernel, cudaFuncAttributeMaxDynamicSharedMemorySize, ATTN_SMEM);

    // 1) fused operand conversion
    conv_all_kernel<<<8192, 256>>>(X, Wqkv, Wproj);

    // 2) QKV GEMM -> fp16 q(scaled)/k/v
    gemm16<1><<<dim3(24, 32), 128, GEMM_SMEM>>>(bqkv, nullptr, 3 * DMODEL);

    // 3) split-KV attention with inline turnstile combine -> g_x16
    attn_mma_kernel<<<dim3(KSPLIT, 32, NH), 128, ATTN_SMEM>>>();

    // 4) proj GEMM -> out
    gemm16<0><<<dim3(8, 32), 128, GEMM_SMEM>>>(bproj, out, DMODEL);
}

// round 15
// speedup vs baseline: 1.0867x; 1.0867x over previous
#include <cuda_runtime.h>
#include <cuda_fp16.h>
#include <cstdint>

#define SEQ  4096
#define DMODEL 1024
#define NH   16
#define HDIM 64
#define KSPLIT 2

// single fp16 A operand: X for QKV GEMM, then combined attention output for proj
__device__ __align__(16) __half g_x16[(long)SEQ * DMODEL];
// single fp16 weights, SAME layout as input: [K][N] (consumed k-major via ldsm.trans)
__device__ __align__(16) __half g_w1[(long)DMODEL * 3 * DMODEL];
__device__ __align__(16) __half g_w2[(long)DMODEL * DMODEL];
// fp16 q/k/v (q pre-scaled by 0.125*log2e), head-major [h][seq][hd]
__device__ __align__(16) __half g_q16[(long)NH * SEQ * HDIM];
__device__ __align__(16) __half g_k16[(long)NH * SEQ * HDIM];
__device__ __align__(16) __half g_v16[(long)NH * SEQ * HDIM];
// split-KV partials: unnormalized O (fp16) + per-row m,l (fp32, exp2 domain)
__device__ __align__(16) __half g_opart[(long)KSPLIT * SEQ * DMODEL];
__device__ float g_pm[(long)KSPLIT * NH * SEQ];
__device__ float g_pl[(long)KSPLIT * NH * SEQ];

#define QSCALE 0.18033688f   // 0.125 * log2(e)

// ---------------------------------------------------------------------------
__device__ __forceinline__ uint32_t smem_u32(const void* p) {
    uint32_t a;
    asm("{ .reg .u64 t; cvta.to.shared.u64 t, %1; cvt.u32.u64 %0, t; }" : "=r"(a) : "l"(p));
    return a;
}
__device__ __forceinline__ float ex2(float x) {
    float y; asm("ex2.approx.f32 %0, %1;" : "=f"(y) : "f"(x)); return y;
}
#define CP16(dst, src) \
    asm volatile("cp.async.cg.shared.global [%0], [%1], 16;" :: "r"(dst), "l"(src))
#define CP_COMMIT() asm volatile("cp.async.commit_group;" ::: "memory")
#define CP_WAIT2()  asm volatile("cp.async.wait_group 2;" ::: "memory")
#define CP_WAIT1()  asm volatile("cp.async.wait_group 1;" ::: "memory")
#define CP_WAIT0()  asm volatile("cp.async.wait_group 0;" ::: "memory")

#define LDSM4(r0, r1, r2, r3, addr) \
    asm volatile("ldmatrix.sync.aligned.m8n8.x4.shared.b16 {%0,%1,%2,%3}, [%4];" \
                 : "=r"(r0), "=r"(r1), "=r"(r2), "=r"(r3) : "r"(addr))
#define LDSM4T(r0, r1, r2, r3, addr) \
    asm volatile("ldmatrix.sync.aligned.m8n8.x4.trans.shared.b16 {%0,%1,%2,%3}, [%4];" \
                 : "=r"(r0), "=r"(r1), "=r"(r2), "=r"(r3) : "r"(addr))

#define MMAH(c, a, b0, b1) \
    asm volatile("mma.sync.aligned.m16n8k16.row.col.f32.f16.f16.f32 " \
                 "{%0,%1,%2,%3}, {%4,%5,%6,%7}, {%8,%9}, {%0,%1,%2,%3};" \
                 : "+f"((c)[0]), "+f"((c)[1]), "+f"((c)[2]), "+f"((c)[3]) \
                 : "r"((a)[0]), "r"((a)[1]), "r"((a)[2]), "r"((a)[3]), \
                   "r"(b0), "r"(b1))

__device__ __forceinline__ uint32_t h2u(__half2 h) { return *(uint32_t*)&h; }

// ---------------------------------------------------------------------------
// Fused conversion kernel: X -> g_x16, Wqkv -> g_w1, Wproj -> g_w2.
// ---------------------------------------------------------------------------
__global__ void conv_all_kernel(const float* __restrict__ X,
                                const float* __restrict__ W1,
                                const float* __restrict__ W2) {
    int b = blockIdx.x;
    const float* src;
    __half* dst;
    int j;
    if (b < 4096)      { src = X;  dst = g_x16; j = b * 256 + threadIdx.x; }
    else if (b < 7168) { src = W1; dst = g_w1;  j = (b - 4096) * 256 + threadIdx.x; }
    else               { src = W2; dst = g_w2;  j = (b - 7168) * 256 + threadIdx.x; }
    float4 v = ((const float4*)src)[j];
    __half2* H = (__half2*)dst;
    H[2*j]   = __floats2half2_rn(v.x, v.y);
    H[2*j+1] = __floats2half2_rn(v.z, v.w);
}

// ---------------------------------------------------------------------------
// Single-fp16 GEMM, 128 threads / 4 warps, warp tile 64x64 (round-12 config).
// ---------------------------------------------------------------------------
template <int MODE>
__global__ __launch_bounds__(128, 2) void gemm16(
    const float* __restrict__ bias, float* __restrict__ C, int N)
{
    const __half* __restrict__ B = MODE ? g_w1 : g_w2;
    const int K = DMODEL;
    extern __shared__ char smem[];
    const uint32_t sb = smem_u32(smem);
    const int tid  = threadIdx.x;
    const int lane = tid & 31;
    const int wid  = tid >> 5;
    const int wm   = wid >> 1;
    const int wn   = wid & 1;
    const int n0 = blockIdx.x * 128, m0 = blockIdx.y * 128;

    float acc[4][8][4];
#pragma unroll
    for (int mt = 0; mt < 4; mt++)
#pragma unroll
        for (int nt = 0; nt < 8; nt++)
#pragma unroll
            for (int r = 0; r < 4; r++) acc[mt][nt][r] = 0.f;

    auto load_stage = [&](int stg, int ck) {
        const uint32_t st = sb + (uint32_t)stg * 32768;
        const int k0 = ck * 64;
#pragma unroll
        for (int it = 0; it < 8; it++) {
            int id  = it * 128 + tid;
            int row = id >> 3, kc = id & 7;
            const void* g = g_x16 + (size_t)(m0 + row) * K + k0 + kc * 8;
            uint32_t soff = (uint32_t)(row * 128 + ((kc * 16) ^ ((row & 7) << 4)));
            CP16(st + soff, g);
        }
#pragma unroll
        for (int it = 0; it < 8; it++) {
            int id  = it * 128 + tid;
            int row = id >> 4, c16 = id & 15;
            const void* g = B + (size_t)(k0 + row) * N + n0 + c16 * 8;
            uint32_t soff = (uint32_t)(row * 256 + ((c16 * 16) ^ ((row & 15) << 4)));
            CP16(st + 16384 + soff, g);
        }
    };

    const int NC = K / 64;
    load_stage(0, 0); CP_COMMIT();
    load_stage(1, 1); CP_COMMIT();

    const int r_lane = lane & 15;
    const int c_lane = (lane >> 4) << 4;
    const uint32_t xorA = (uint32_t)((r_lane & 7) << 4);
    const uint32_t xorB = (uint32_t)(r_lane << 4);
    const uint32_t colB = (uint32_t)(wn * 128 + c_lane);

    for (int c = 0; c < NC; c++) {
        if (c + 1 < NC) { CP_WAIT1(); } else { CP_WAIT0(); }
        __syncthreads();
        if (c + 2 < NC) { load_stage((c + 2) % 3, c + 2); CP_COMMIT(); }

        const uint32_t st = sb + (uint32_t)(c % 3) * 32768;
        const uint32_t aA = st +         (uint32_t)((wm * 64 + r_lane) * 128);
        const uint32_t rB = st + 16384 + (uint32_t)(r_lane * 256);

#pragma unroll
        for (int ks = 0; ks < 4; ks++) {
            const uint32_t cvA = ((uint32_t)(ks * 32 + c_lane)) ^ xorA;
            uint32_t ah[4][4], bh[4][4];
#pragma unroll
            for (int mt = 0; mt < 4; mt++)
                LDSM4(ah[mt][0], ah[mt][1], ah[mt][2], ah[mt][3], aA + mt * 2048 + cvA);
#pragma unroll
            for (int bn = 0; bn < 4; bn++)
                LDSM4T(bh[bn][0], bh[bn][1], bh[bn][2], bh[bn][3],
                       rB + ks * 4096 + ((colB + bn * 32) ^ xorB));
#pragma unroll
            for (int mt = 0; mt < 4; mt++)
#pragma unroll
                for (int nt = 0; nt < 8; nt++) {
                    int bn = nt >> 1, sub = nt & 1;
                    MMAH(acc[mt][nt], ah[mt], bh[bn][sub * 2], bh[bn][sub * 2 + 1]);
                }
        }
    }

    const int rq = lane >> 2;
    const int cq = (lane & 3) * 2;
#pragma unroll
    for (int mt = 0; mt < 4; mt++) {
#pragma unroll
        for (int nt = 0; nt < 8; nt++) {
            int gcol = n0 + wn * 64 + nt * 8 + cq;
            float b0 = bias[gcol], b1 = bias[gcol + 1];
            if (MODE == 1) {
                int sect = gcol >> 10, w = gcol & 1023;
                int hh = w >> 6, dd = w & 63;
                __half* dst = (sect == 0) ? g_q16 : (sect == 1) ? g_k16 : g_v16;
                float sc = (sect == 0) ? QSCALE : 1.0f;
#pragma unroll
                for (int half = 0; half < 2; half++) {
                    int grow = m0 + wm * 64 + mt * 16 + rq + half * 8;
                    float vx = (acc[mt][nt][half * 2 + 0] + b0) * sc;
                    float vy = (acc[mt][nt][half * 2 + 1] + b1) * sc;
                    *(__half2*)&dst[((size_t)hh * SEQ + grow) * HDIM + dd] =
                        __floats2half2_rn(vx, vy);
                }
            } else {
#pragma unroll
                for (int half = 0; half < 2; half++) {
                    int grow = m0 + wm * 64 + mt * 16 + rq + half * 8;
                    float2 v;
                    v.x = acc[mt][nt][half * 2 + 0] + b0;
                    v.y = acc[mt][nt][half * 2 + 1] + b1;
                    *(float2*)&C[(size_t)grow * N + gcol] = v;
                }
            }
        }
    }
}

// ---------------------------------------------------------------------------
// FlashAttention-2, split-KV x2, 4 warps x 32 rows, fp16 partials.
// 4-stage KV pipeline (80KB smem), one __syncthreads per tile, 2 CTAs/SM.
// Separate combine kernel (round-13 structure — turnstile regressed).
// ---------------------------------------------------------------------------
__global__ __launch_bounds__(128, 2) void attn_mma_kernel()
{
    extern __shared__ char smem[];
    const uint32_t sb = smem_u32(smem);
    const int tid = threadIdx.x, lane = tid & 31, wid = tid >> 5;
    const int sp = blockIdx.x;
    const int iq = 31 - (int)blockIdx.y;     // heavy blocks first
    const int h  = blockIdx.z;
    const int jbeg = sp * (iq + 1);
    const int jend = jbeg + iq + 1;

    const uint32_t Qs = sb;                  // 16KB

    auto load_kv = [&](int stg, int j) {
        const uint32_t st = sb + 16384 + (uint32_t)stg * 16384;
#pragma unroll
        for (int a = 0; a < 2; a++) {
            const __half* src = a ? g_v16 : g_k16;
#pragma unroll
            for (int it = 0; it < 4; it++) {
                int id = it * 128 + tid;
                int row = id >> 3, kc = id & 7;
                uint32_t soff = (uint32_t)(row * 128 + ((kc * 16) ^ ((row & 7) << 4)));
                CP16(st + a * 8192 + soff,
                     src + ((size_t)h * SEQ + j * 64 + row) * HDIM + kc * 8);
            }
        }
    };

    {
#pragma unroll
        for (int it = 0; it < 8; it++) {
            int id = it * 128 + tid;
            int row = id >> 3, kc = id & 7;
            uint32_t soff = (uint32_t)(row * 128 + ((kc * 16) ^ ((row & 7) << 4)));
            CP16(Qs + soff, g_q16 + ((size_t)h * SEQ + iq * 128 + row) * HDIM + kc * 8);
        }
        load_kv(0, jbeg);
        CP_COMMIT();
        if (jbeg + 1 < jend) { load_kv(1, jbeg + 1); CP_COMMIT(); }
        if (jbeg + 2 < jend) { load_kv(2, jbeg + 2); CP_COMMIT(); }
    }

    float o[2][8][4];
#pragma unroll
    for (int mt = 0; mt < 2; mt++)
#pragma unroll
        for (int nt = 0; nt < 8; nt++)
#pragma unroll
            for (int r = 0; r < 4; r++) o[mt][nt][r] = 0.f;
    float mst[2][2], lst[2][2];
#pragma unroll
    for (int mt = 0; mt < 2; mt++) { mst[mt][0] = mst[mt][1] = -1e30f;
                                     lst[mt][0] = lst[mt][1] = 0.f; }
    uint32_t qf[2][4][4];

    const uint32_t xorterm = (uint32_t)((lane & 7) << 4);
    const uint32_t c_lane  = (uint32_t)((lane >> 4) << 4);
    int r0g[2];
#pragma unroll
    for (int mt = 0; mt < 2; mt++)
        r0g[mt] = iq * 128 + wid * 32 + mt * 16 + (lane >> 2);

    for (int j = jbeg; j < jend; j++) {
        const int jj = j - jbeg;
        if (j + 2 < jend)      { CP_WAIT2(); }
        else if (j + 1 < jend) { CP_WAIT1(); }
        else                   { CP_WAIT0(); }
        __syncthreads();
        if (j + 3 < jend) { load_kv((jj + 3) & 3, j + 3); CP_COMMIT(); }

        if (jj == 0) {
#pragma unroll
            for (int mt = 0; mt < 2; mt++) {
                const uint32_t qrow = Qs +
                    (uint32_t)((wid * 32 + mt * 16 + (lane & 15)) * 128);
#pragma unroll
                for (int ks = 0; ks < 4; ks++) {
                    uint32_t cv = ((uint32_t)(ks * 32) + c_lane) ^ xorterm;
                    LDSM4(qf[mt][ks][0], qf[mt][ks][1], qf[mt][ks][2], qf[mt][ks][3],
                          qrow + cv);
                }
            }
        }

        const uint32_t st = sb + 16384 + (uint32_t)(jj & 3) * 16384;
        const uint32_t Ks = st, Vs = st + 8192;

        float s[2][8][4];
#pragma unroll
        for (int mt = 0; mt < 2; mt++)
#pragma unroll
            for (int nt = 0; nt < 8; nt++)
#pragma unroll
                for (int r = 0; r < 4; r++) s[mt][nt][r] = 0.f;

#pragma unroll
        for (int ks = 0; ks < 4; ks++) {
            uint32_t cv = ((uint32_t)(ks * 32) + c_lane) ^ xorterm;
#pragma unroll
            for (int bn = 0; bn < 4; bn++) {
                uint32_t kh[4];
                LDSM4(kh[0], kh[1], kh[2], kh[3],
                      Ks + (uint32_t)((bn * 16 + (lane & 15)) * 128) + cv);
#pragma unroll
                for (int mt = 0; mt < 2; mt++)
#pragma unroll
                    for (int sub = 0; sub < 2; sub++)
                        MMAH(s[mt][bn * 2 + sub], qf[mt][ks], kh[sub], kh[sub + 2]);
            }
        }

        if (j >= 2 * iq) {
            int cbase = j * 64 + (lane & 3) * 2;
#pragma unroll
            for (int mt = 0; mt < 2; mt++)
#pragma unroll
                for (int nt = 0; nt < 8; nt++) {
                    int c0 = cbase + nt * 8, c1 = c0 + 1;
                    if (c0 > r0g[mt])     s[mt][nt][0] = -1e30f;
                    if (c1 > r0g[mt])     s[mt][nt][1] = -1e30f;
                    if (c0 > r0g[mt] + 8) s[mt][nt][2] = -1e30f;
                    if (c1 > r0g[mt] + 8) s[mt][nt][3] = -1e30f;
                }
        }

#pragma unroll
        for (int mt = 0; mt < 2; mt++) {
            float mx0 = -1e30f, mx1 = -1e30f;
#pragma unroll
            for (int nt = 0; nt < 8; nt++) {
                mx0 = fmaxf(mx0, fmaxf(s[mt][nt][0], s[mt][nt][1]));
                mx1 = fmaxf(mx1, fmaxf(s[mt][nt][2], s[mt][nt][3]));
            }
            mx0 = fmaxf(mx0, __shfl_xor_sync(0xFFFFFFFFu, mx0, 1));
            mx0 = fmaxf(mx0, __shfl_xor_sync(0xFFFFFFFFu, mx0, 2));
            mx1 = fmaxf(mx1, __shfl_xor_sync(0xFFFFFFFFu, mx1, 1));
            mx1 = fmaxf(mx1, __shfl_xor_sync(0xFFFFFFFFu, mx1, 2));
            float mn0 = fmaxf(mst[mt][0], mx0), mn1 = fmaxf(mst[mt][1], mx1);
            float al0 = ex2(mst[mt][0] - mn0), al1 = ex2(mst[mt][1] - mn1);
            mst[mt][0] = mn0; mst[mt][1] = mn1;

            float sum0 = 0.f, sum1 = 0.f;
#pragma unroll
            for (int nt = 0; nt < 8; nt++) {
                s[mt][nt][0] = ex2(s[mt][nt][0] - mn0);
                s[mt][nt][1] = ex2(s[mt][nt][1] - mn0);
                s[mt][nt][2] = ex2(s[mt][nt][2] - mn1);
                s[mt][nt][3] = ex2(s[mt][nt][3] - mn1);
                sum0 += s[mt][nt][0] + s[mt][nt][1];
                sum1 += s[mt][nt][2] + s[mt][nt][3];
            }
            sum0 += __shfl_xor_sync(0xFFFFFFFFu, sum0, 1);
            sum0 += __shfl_xor_sync(0xFFFFFFFFu, sum0, 2);
            sum1 += __shfl_xor_sync(0xFFFFFFFFu, sum1, 1);
            sum1 += __shfl_xor_sync(0xFFFFFFFFu, sum1, 2);
            lst[mt][0] = lst[mt][0] * al0 + sum0;
            lst[mt][1] = lst[mt][1] * al1 + sum1;

#pragma unroll
            for (int nt = 0; nt < 8; nt++) {
                o[mt][nt][0] *= al0; o[mt][nt][1] *= al0;
                o[mt][nt][2] *= al1; o[mt][nt][3] *= al1;
            }
        }

#pragma unroll
        for (int t = 0; t < 4; t++) {
            uint32_t ap[2][4];
#pragma unroll
            for (int mt = 0; mt < 2; mt++)
#pragma unroll
                for (int u = 0; u < 4; u++) {
                    int nt = t * 2 + (u >> 1);
                    int base = (u & 1) * 2;
                    ap[mt][u] = h2u(__floats2half2_rn(s[mt][nt][base],
                                                      s[mt][nt][base + 1]));
                }
            uint32_t rowoff = (uint32_t)((t * 16 + (lane & 15)) * 128);
#pragma unroll
            for (int g = 0; g < 4; g++) {
                uint32_t cvv = ((uint32_t)(g * 32) + c_lane) ^ xorterm;
                uint32_t vh[4];
                LDSM4T(vh[0], vh[1], vh[2], vh[3], Vs + rowoff + cvv);
#pragma unroll
                for (int mt = 0; mt < 2; mt++) {
                    MMAH(o[mt][g * 2],     ap[mt], vh[0], vh[1]);
                    MMAH(o[mt][g * 2 + 1], ap[mt], vh[2], vh[3]);
                }
            }
        }
    }

    // ---- write unnormalized partials (fp16) + m,l ----
    __half* Op = g_opart + (size_t)sp * SEQ * DMODEL;
    int colb = h * 64 + (lane & 3) * 2;
#pragma unroll
    for (int mt = 0; mt < 2; mt++) {
#pragma unroll
        for (int nt = 0; nt < 8; nt++) {
            int col = colb + nt * 8;
            size_t i0 = (size_t)r0g[mt] * DMODEL + col;
            size_t i1 = (size_t)(r0g[mt] + 8) * DMODEL + col;
            *(__half2*)&Op[i0] = __floats2half2_rn(o[mt][nt][0], o[mt][nt][1]);
            *(__half2*)&Op[i1] = __floats2half2_rn(o[mt][nt][2], o[mt][nt][3]);
        }
        if ((lane & 3) == 0) {
            size_t base = (size_t)sp * NH * SEQ + (size_t)h * SEQ;
            g_pm[base + r0g[mt]]     = mst[mt][0];
            g_pm[base + r0g[mt] + 8] = mst[mt][1];
            g_pl[base + r0g[mt]]     = lst[mt][0];
            g_pl[base + r0g[mt] + 8] = lst[mt][1];
        }
    }
}

// ---------------------------------------------------------------------------
// Combine split-KV partials (exp2 domain) -> fp16 proj input. uint4 I/O:
// each thread handles 8 consecutive halves per partial.
// ---------------------------------------------------------------------------
__global__ void combine_kernel()
{
    int idx = blockIdx.x * 256 + threadIdx.x;   // uint4 index over SEQ*DMODEL/8
    int row = idx >> 7;                          // 128 uint4-groups per row
    int h   = (idx & 127) >> 3;                  // 8 groups per head
    size_t mlb = (size_t)h * SEQ + row;
    float m0 = g_pm[mlb], m1 = g_pm[(size_t)NH * SEQ + mlb];
    float l0 = g_pl[mlb], l1 = g_pl[(size_t)NH * SEQ + mlb];
    float ms = fmaxf(m0, m1);
    float w0 = ex2(m0 - ms), w1 = ex2(m1 - ms);
    float inv = 1.0f / (w0 * l0 + w1 * l1);
    w0 *= inv; w1 *= inv;
    uint4 ua = ((const uint4*)g_opart)[idx];
    uint4 ub = ((const uint4*)(g_opart + (size_t)SEQ * DMODEL))[idx];
    uint4 uo;
    __half2* pa = (__half2*)&ua;
    __half2* pb = (__half2*)&ub;
    __half2* po = (__half2*)&uo;
#pragma unroll
    for (int q = 0; q < 4; q++) {
        float2 fa = __half22float2(pa[q]);
        float2 fb = __half22float2(pb[q]);
        po[q] = __floats2half2_rn(fa.x * w0 + fb.x * w1, fa.y * w0 + fb.y * w1);
    }
    ((uint4*)g_x16)[idx] = uo;
}

// ---------------------------------------------------------------------------
extern "C" void kernel_launch(void* const* d_in, const int* in_sizes, int n_in,
                              void* d_out, int out_size)
{
    const float* X     = (const float*)d_in[0];
    const float* Wqkv  = (const float*)d_in[1];
    const float* bqkv  = (const float*)d_in[2];
    const float* Wproj = (const float*)d_in[3];
    const float* bproj = (const float*)d_in[4];
    float* out = (float*)d_out;

    const int GEMM_SMEM = 3 * 2 * 16384;             // 98304 B, 2 CTAs/SM
    const int ATTN_SMEM = 16384 + 4 * 16384;         // 81920 B, 2 CTAs/SM
    cudaFuncSetAttribute(gemm16<1>, cudaFuncAttributeMaxDynamicSharedMemorySize, GEMM_SMEM);
    cudaFuncSetAttribute(gemm16<0>, cudaFuncAttributeMaxDynamicSharedMemorySize, GEMM_SMEM);
    cudaFuncSetAttribute(attn_mma_kernel, cudaFuncAttributeMaxDynamicSharedMemorySize, ATTN_SMEM);

    // 1) fused operand conversion
    conv_all_kernel<<<8192, 256>>>(X, Wqkv, Wproj);

    // 2) QKV GEMM -> fp16 q(scaled)/k/v
    gemm16<1><<<dim3(24, 32), 128, GEMM_SMEM>>>(bqkv, nullptr, 3 * DMODEL);

    // 3) split-KV attention (fp16 partials) + separate combine -> g_x16
    attn_mma_kernel<<<dim3(KSPLIT, 32, NH), 128, ATTN_SMEM>>>();
    combine_kernel<<<SEQ * DMODEL / 8 / 256, 256>>>();

    // 4) proj GEMM -> out
    gemm16<0><<<dim3(8, 32), 128, GEMM_SMEM>>>(bproj, out, DMODEL);
}

// round 16
// speedup vs baseline: 1.1908x; 1.0958x over previous
#include <cuda_runtime.h>
#include <cuda_fp16.h>
#include <cstdint>

#define SEQ  4096
#define DMODEL 1024
#define NH   16
#define HDIM 64
#define KSPLIT 2

// single fp16 A operand: X for QKV GEMM, then combined attention output for proj
__device__ __align__(16) __half g_x16[(long)SEQ * DMODEL];
// single fp16 weights, SAME layout as input: [K][N] (consumed k-major via ldsm.trans)
__device__ __align__(16) __half g_w1[(long)DMODEL * 3 * DMODEL];
__device__ __align__(16) __half g_w2[(long)DMODEL * DMODEL];
// fp16 q/k/v (q pre-scaled by 0.125*log2e), head-major [h][seq][hd]
__device__ __align__(16) __half g_q16[(long)NH * SEQ * HDIM];
__device__ __align__(16) __half g_k16[(long)NH * SEQ * HDIM];
__device__ __align__(16) __half g_v16[(long)NH * SEQ * HDIM];
// split-KV partials: unnormalized O (fp16) + per-row packed (m,l) (fp32 exp2 domain)
__device__ __align__(16) __half g_opart[(long)KSPLIT * SEQ * DMODEL];
__device__ __align__(8) float2 g_pml[(long)KSPLIT * NH * SEQ];

#define QSCALE 0.18033688f   // 0.125 * log2(e)

// ---------------------------------------------------------------------------
__device__ __forceinline__ uint32_t smem_u32(const void* p) {
    uint32_t a;
    asm("{ .reg .u64 t; cvta.to.shared.u64 t, %1; cvt.u32.u64 %0, t; }" : "=r"(a) : "l"(p));
    return a;
}
__device__ __forceinline__ float ex2(float x) {
    float y; asm("ex2.approx.f32 %0, %1;" : "=f"(y) : "f"(x)); return y;
}
#define CP16(dst, src) \
    asm volatile("cp.async.cg.shared.global [%0], [%1], 16;" :: "r"(dst), "l"(src))
#define CP_COMMIT() asm volatile("cp.async.commit_group;" ::: "memory")
#define CP_WAIT2()  asm volatile("cp.async.wait_group 2;" ::: "memory")
#define CP_WAIT1()  asm volatile("cp.async.wait_group 1;" ::: "memory")
#define CP_WAIT0()  asm volatile("cp.async.wait_group 0;" ::: "memory")

#define LDSM4(r0, r1, r2, r3, addr) \
    asm volatile("ldmatrix.sync.aligned.m8n8.x4.shared.b16 {%0,%1,%2,%3}, [%4];" \
                 : "=r"(r0), "=r"(r1), "=r"(r2), "=r"(r3) : "r"(addr))
#define LDSM4T(r0, r1, r2, r3, addr) \
    asm volatile("ldmatrix.sync.aligned.m8n8.x4.trans.shared.b16 {%0,%1,%2,%3}, [%4];" \
                 : "=r"(r0), "=r"(r1), "=r"(r2), "=r"(r3) : "r"(addr))

#define MMAH(c, a, b0, b1) \
    asm volatile("mma.sync.aligned.m16n8k16.row.col.f32.f16.f16.f32 " \
                 "{%0,%1,%2,%3}, {%4,%5,%6,%7}, {%8,%9}, {%0,%1,%2,%3};" \
                 : "+f"((c)[0]), "+f"((c)[1]), "+f"((c)[2]), "+f"((c)[3]) \
                 : "r"((a)[0]), "r"((a)[1]), "r"((a)[2]), "r"((a)[3]), \
                   "r"(b0), "r"(b1))

__device__ __forceinline__ uint32_t h2u(__half2 h) { return *(uint32_t*)&h; }

// ---------------------------------------------------------------------------
// Fused conversion kernel: X -> g_x16, Wqkv -> g_w1, Wproj -> g_w2.
// ---------------------------------------------------------------------------
__global__ void conv_all_kernel(const float* __restrict__ X,
                                const float* __restrict__ W1,
                                const float* __restrict__ W2) {
    int b = blockIdx.x;
    const float* src;
    __half* dst;
    int j;
    if (b < 4096)      { src = X;  dst = g_x16; j = b * 256 + threadIdx.x; }
    else if (b < 7168) { src = W1; dst = g_w1;  j = (b - 4096) * 256 + threadIdx.x; }
    else               { src = W2; dst = g_w2;  j = (b - 7168) * 256 + threadIdx.x; }
    float4 v = ((const float4*)src)[j];
    __half2* H = (__half2*)dst;
    H[2*j]   = __floats2half2_rn(v.x, v.y);
    H[2*j+1] = __floats2half2_rn(v.z, v.w);
}

// ---------------------------------------------------------------------------
// Single-fp16 GEMM, 128 threads / 4 warps, warp tile 64x64 (round-12 config).
// ---------------------------------------------------------------------------
template <int MODE>
__global__ __launch_bounds__(128, 2) void gemm16(
    const float* __restrict__ bias, float* __restrict__ C, int N)
{
    const __half* __restrict__ B = MODE ? g_w1 : g_w2;
    const int K = DMODEL;
    extern __shared__ char smem[];
    const uint32_t sb = smem_u32(smem);
    const int tid  = threadIdx.x;
    const int lane = tid & 31;
    const int wid  = tid >> 5;
    const int wm   = wid >> 1;
    const int wn   = wid & 1;
    const int n0 = blockIdx.x * 128, m0 = blockIdx.y * 128;

    float acc[4][8][4];
#pragma unroll
    for (int mt = 0; mt < 4; mt++)
#pragma unroll
        for (int nt = 0; nt < 8; nt++)
#pragma unroll
            for (int r = 0; r < 4; r++) acc[mt][nt][r] = 0.f;

    auto load_stage = [&](int stg, int ck) {
        const uint32_t st = sb + (uint32_t)stg * 32768;
        const int k0 = ck * 64;
#pragma unroll
        for (int it = 0; it < 8; it++) {
            int id  = it * 128 + tid;
            int row = id >> 3, kc = id & 7;
            const void* g = g_x16 + (size_t)(m0 + row) * K + k0 + kc * 8;
            uint32_t soff = (uint32_t)(row * 128 + ((kc * 16) ^ ((row & 7) << 4)));
            CP16(st + soff, g);
        }
#pragma unroll
        for (int it = 0; it < 8; it++) {
            int id  = it * 128 + tid;
            int row = id >> 4, c16 = id & 15;
            const void* g = B + (size_t)(k0 + row) * N + n0 + c16 * 8;
            uint32_t soff = (uint32_t)(row * 256 + ((c16 * 16) ^ ((row & 15) << 4)));
            CP16(st + 16384 + soff, g);
        }
    };

    const int NC = K / 64;
    load_stage(0, 0); CP_COMMIT();
    load_stage(1, 1); CP_COMMIT();

    const int r_lane = lane & 15;
    const int c_lane = (lane >> 4) << 4;
    const uint32_t xorA = (uint32_t)((r_lane & 7) << 4);
    const uint32_t xorB = (uint32_t)(r_lane << 4);
    const uint32_t colB = (uint32_t)(wn * 128 + c_lane);

    for (int c = 0; c < NC; c++) {
        if (c + 1 < NC) { CP_WAIT1(); } else { CP_WAIT0(); }
        __syncthreads();
        if (c + 2 < NC) { load_stage((c + 2) % 3, c + 2); CP_COMMIT(); }

        const uint32_t st = sb + (uint32_t)(c % 3) * 32768;
        const uint32_t aA = st +         (uint32_t)((wm * 64 + r_lane) * 128);
        const uint32_t rB = st + 16384 + (uint32_t)(r_lane * 256);

#pragma unroll
        for (int ks = 0; ks < 4; ks++) {
            const uint32_t cvA = ((uint32_t)(ks * 32 + c_lane)) ^ xorA;
            uint32_t ah[4][4], bh[4][4];
#pragma unroll
            for (int mt = 0; mt < 4; mt++)
                LDSM4(ah[mt][0], ah[mt][1], ah[mt][2], ah[mt][3], aA + mt * 2048 + cvA);
#pragma unroll
            for (int bn = 0; bn < 4; bn++)
                LDSM4T(bh[bn][0], bh[bn][1], bh[bn][2], bh[bn][3],
                       rB + ks * 4096 + ((colB + bn * 32) ^ xorB));
#pragma unroll
            for (int mt = 0; mt < 4; mt++)
#pragma unroll
                for (int nt = 0; nt < 8; nt++) {
                    int bn = nt >> 1, sub = nt & 1;
                    MMAH(acc[mt][nt], ah[mt], bh[bn][sub * 2], bh[bn][sub * 2 + 1]);
                }
        }
    }

    const int rq = lane >> 2;
    const int cq = (lane & 3) * 2;
#pragma unroll
    for (int mt = 0; mt < 4; mt++) {
#pragma unroll
        for (int nt = 0; nt < 8; nt++) {
            int gcol = n0 + wn * 64 + nt * 8 + cq;
            float b0 = bias[gcol], b1 = bias[gcol + 1];
            if (MODE == 1) {
                int sect = gcol >> 10, w = gcol & 1023;
                int hh = w >> 6, dd = w & 63;
                __half* dst = (sect == 0) ? g_q16 : (sect == 1) ? g_k16 : g_v16;
                float sc = (sect == 0) ? QSCALE : 1.0f;
#pragma unroll
                for (int half = 0; half < 2; half++) {
                    int grow = m0 + wm * 64 + mt * 16 + rq + half * 8;
                    float vx = (acc[mt][nt][half * 2 + 0] + b0) * sc;
                    float vy = (acc[mt][nt][half * 2 + 1] + b1) * sc;
                    *(__half2*)&dst[((size_t)hh * SEQ + grow) * HDIM + dd] =
                        __floats2half2_rn(vx, vy);
                }
            } else {
#pragma unroll
                for (int half = 0; half < 2; half++) {
                    int grow = m0 + wm * 64 + mt * 16 + rq + half * 8;
                    float2 v;
                    v.x = acc[mt][nt][half * 2 + 0] + b0;
                    v.y = acc[mt][nt][half * 2 + 1] + b1;
                    *(float2*)&C[(size_t)grow * N + gcol] = v;
                }
            }
        }
    }
}

// ---------------------------------------------------------------------------
// FlashAttention-2, split-KV x2, 4 warps x 32 rows, fp16 partials.
// Grid (KSPLIT, NH, 32) with q-block on the SLOWEST axis, heavy-first:
// all 32-tile CTAs (every head) land in the first wave (LPT schedule).
// 4-stage KV pipeline (80KB smem), one __syncthreads per tile, 2 CTAs/SM.
// ---------------------------------------------------------------------------
__global__ __launch_bounds__(128, 2) void attn_mma_kernel()
{
    extern __shared__ char smem[];
    const uint32_t sb = smem_u32(smem);
    const int tid = threadIdx.x, lane = tid & 31, wid = tid >> 5;
    const int sp = blockIdx.x;
    const int h  = blockIdx.y;
    const int iq = 31 - (int)blockIdx.z;     // heavy blocks first, globally
    const int jbeg = sp * (iq + 1);
    const int jend = jbeg + iq + 1;

    const uint32_t Qs = sb;                  // 16KB

    auto load_kv = [&](int stg, int j) {
        const uint32_t st = sb + 16384 + (uint32_t)stg * 16384;
#pragma unroll
        for (int a = 0; a < 2; a++) {
            const __half* src = a ? g_v16 : g_k16;
#pragma unroll
            for (int it = 0; it < 4; it++) {
                int id = it * 128 + tid;
                int row = id >> 3, kc = id & 7;
                uint32_t soff = (uint32_t)(row * 128 + ((kc * 16) ^ ((row & 7) << 4)));
                CP16(st + a * 8192 + soff,
                     src + ((size_t)h * SEQ + j * 64 + row) * HDIM + kc * 8);
            }
        }
    };

    {
#pragma unroll
        for (int it = 0; it < 8; it++) {
            int id = it * 128 + tid;
            int row = id >> 3, kc = id & 7;
            uint32_t soff = (uint32_t)(row * 128 + ((kc * 16) ^ ((row & 7) << 4)));
            CP16(Qs + soff, g_q16 + ((size_t)h * SEQ + iq * 128 + row) * HDIM + kc * 8);
        }
        load_kv(0, jbeg);
        CP_COMMIT();
        if (jbeg + 1 < jend) { load_kv(1, jbeg + 1); CP_COMMIT(); }
        if (jbeg + 2 < jend) { load_kv(2, jbeg + 2); CP_COMMIT(); }
    }

    float o[2][8][4];
#pragma unroll
    for (int mt = 0; mt < 2; mt++)
#pragma unroll
        for (int nt = 0; nt < 8; nt++)
#pragma unroll
            for (int r = 0; r < 4; r++) o[mt][nt][r] = 0.f;
    float mst[2][2], lst[2][2];
#pragma unroll
    for (int mt = 0; mt < 2; mt++) { mst[mt][0] = mst[mt][1] = -1e30f;
                                     lst[mt][0] = lst[mt][1] = 0.f; }
    uint32_t qf[2][4][4];

    const uint32_t xorterm = (uint32_t)((lane & 7) << 4);
    const uint32_t c_lane  = (uint32_t)((lane >> 4) << 4);
    int r0g[2];
#pragma unroll
    for (int mt = 0; mt < 2; mt++)
        r0g[mt] = iq * 128 + wid * 32 + mt * 16 + (lane >> 2);

    for (int j = jbeg; j < jend; j++) {
        const int jj = j - jbeg;
        if (j + 2 < jend)      { CP_WAIT2(); }
        else if (j + 1 < jend) { CP_WAIT1(); }
        else                   { CP_WAIT0(); }
        __syncthreads();
        if (j + 3 < jend) { load_kv((jj + 3) & 3, j + 3); CP_COMMIT(); }

        if (jj == 0) {
#pragma unroll
            for (int mt = 0; mt < 2; mt++) {
                const uint32_t qrow = Qs +
                    (uint32_t)((wid * 32 + mt * 16 + (lane & 15)) * 128);
#pragma unroll
                for (int ks = 0; ks < 4; ks++) {
                    uint32_t cv = ((uint32_t)(ks * 32) + c_lane) ^ xorterm;
                    LDSM4(qf[mt][ks][0], qf[mt][ks][1], qf[mt][ks][2], qf[mt][ks][3],
                          qrow + cv);
                }
            }
        }

        const uint32_t st = sb + 16384 + (uint32_t)(jj & 3) * 16384;
        const uint32_t Ks = st, Vs = st + 8192;

        float s[2][8][4];
#pragma unroll
        for (int mt = 0; mt < 2; mt++)
#pragma unroll
            for (int nt = 0; nt < 8; nt++)
#pragma unroll
                for (int r = 0; r < 4; r++) s[mt][nt][r] = 0.f;

#pragma unroll
        for (int ks = 0; ks < 4; ks++) {
            uint32_t cv = ((uint32_t)(ks * 32) + c_lane) ^ xorterm;
#pragma unroll
            for (int bn = 0; bn < 4; bn++) {
                uint32_t kh[4];
                LDSM4(kh[0], kh[1], kh[2], kh[3],
                      Ks + (uint32_t)((bn * 16 + (lane & 15)) * 128) + cv);
#pragma unroll
                for (int mt = 0; mt < 2; mt++)
#pragma unroll
                    for (int sub = 0; sub < 2; sub++)
                        MMAH(s[mt][bn * 2 + sub], qf[mt][ks], kh[sub], kh[sub + 2]);
            }
        }

        if (j >= 2 * iq) {
            int cbase = j * 64 + (lane & 3) * 2;
#pragma unroll
            for (int mt = 0; mt < 2; mt++)
#pragma unroll
                for (int nt = 0; nt < 8; nt++) {
                    int c0 = cbase + nt * 8, c1 = c0 + 1;
                    if (c0 > r0g[mt])     s[mt][nt][0] = -1e30f;
                    if (c1 > r0g[mt])     s[mt][nt][1] = -1e30f;
                    if (c0 > r0g[mt] + 8) s[mt][nt][2] = -1e30f;
                    if (c1 > r0g[mt] + 8) s[mt][nt][3] = -1e30f;
                }
        }

#pragma unroll
        for (int mt = 0; mt < 2; mt++) {
            float mx0 = -1e30f, mx1 = -1e30f;
#pragma unroll
            for (int nt = 0; nt < 8; nt++) {
                mx0 = fmaxf(mx0, fmaxf(s[mt][nt][0], s[mt][nt][1]));
                mx1 = fmaxf(mx1, fmaxf(s[mt][nt][2], s[mt][nt][3]));
            }
            mx0 = fmaxf(mx0, __shfl_xor_sync(0xFFFFFFFFu, mx0, 1));
            mx0 = fmaxf(mx0, __shfl_xor_sync(0xFFFFFFFFu, mx0, 2));
            mx1 = fmaxf(mx1, __shfl_xor_sync(0xFFFFFFFFu, mx1, 1));
            mx1 = fmaxf(mx1, __shfl_xor_sync(0xFFFFFFFFu, mx1, 2));
            float mn0 = fmaxf(mst[mt][0], mx0), mn1 = fmaxf(mst[mt][1], mx1);
            float al0 = ex2(mst[mt][0] - mn0), al1 = ex2(mst[mt][1] - mn1);
            mst[mt][0] = mn0; mst[mt][1] = mn1;

            float sum0 = 0.f, sum1 = 0.f;
#pragma unroll
            for (int nt = 0; nt < 8; nt++) {
                s[mt][nt][0] = ex2(s[mt][nt][0] - mn0);
                s[mt][nt][1] = ex2(s[mt][nt][1] - mn0);
                s[mt][nt][2] = ex2(s[mt][nt][2] - mn1);
                s[mt][nt][3] = ex2(s[mt][nt][3] - mn1);
                sum0 += s[mt][nt][0] + s[mt][nt][1];
                sum1 += s[mt][nt][2] + s[mt][nt][3];
            }
            sum0 += __shfl_xor_sync(0xFFFFFFFFu, sum0, 1);
            sum0 += __shfl_xor_sync(0xFFFFFFFFu, sum0, 2);
            sum1 += __shfl_xor_sync(0xFFFFFFFFu, sum1, 1);
            sum1 += __shfl_xor_sync(0xFFFFFFFFu, sum1, 2);
            lst[mt][0] = lst[mt][0] * al0 + sum0;
            lst[mt][1] = lst[mt][1] * al1 + sum1;

#pragma unroll
            for (int nt = 0; nt < 8; nt++) {
                o[mt][nt][0] *= al0; o[mt][nt][1] *= al0;
                o[mt][nt][2] *= al1; o[mt][nt][3] *= al1;
            }
        }

#pragma unroll
        for (int t = 0; t < 4; t++) {
            uint32_t ap[2][4];
#pragma unroll
            for (int mt = 0; mt < 2; mt++)
#pragma unroll
                for (int u = 0; u < 4; u++) {
                    int nt = t * 2 + (u >> 1);
                    int base = (u & 1) * 2;
                    ap[mt][u] = h2u(__floats2half2_rn(s[mt][nt][base],
                                                      s[mt][nt][base + 1]));
                }
            uint32_t rowoff = (uint32_t)((t * 16 + (lane & 15)) * 128);
#pragma unroll
            for (int g = 0; g < 4; g++) {
                uint32_t cvv = ((uint32_t)(g * 32) + c_lane) ^ xorterm;
                uint32_t vh[4];
                LDSM4T(vh[0], vh[1], vh[2], vh[3], Vs + rowoff + cvv);
#pragma unroll
                for (int mt = 0; mt < 2; mt++) {
                    MMAH(o[mt][g * 2],     ap[mt], vh[0], vh[1]);
                    MMAH(o[mt][g * 2 + 1], ap[mt], vh[2], vh[3]);
                }
            }
        }
    }

    // ---- write unnormalized partials (fp16) + packed (m,l) ----
    __half* Op = g_opart + (size_t)sp * SEQ * DMODEL;
    int colb = h * 64 + (lane & 3) * 2;
#pragma unroll
    for (int mt = 0; mt < 2; mt++) {
#pragma unroll
        for (int nt = 0; nt < 8; nt++) {
            int col = colb + nt * 8;
            size_t i0 = (size_t)r0g[mt] * DMODEL + col;
            size_t i1 = (size_t)(r0g[mt] + 8) * DMODEL + col;
            *(__half2*)&Op[i0] = __floats2half2_rn(o[mt][nt][0], o[mt][nt][1]);
            *(__half2*)&Op[i1] = __floats2half2_rn(o[mt][nt][2], o[mt][nt][3]);
        }
        if ((lane & 3) == 0) {
            size_t base = (size_t)sp * NH * SEQ + (size_t)h * SEQ;
            float2 a; a.x = mst[mt][0]; a.y = lst[mt][0];
            float2 b; b.x = mst[mt][1]; b.y = lst[mt][1];
            g_pml[base + r0g[mt]]     = a;
            g_pml[base + r0g[mt] + 8] = b;
        }
    }
}

// ---------------------------------------------------------------------------
// Combine split-KV partials (exp2 domain) -> fp16 proj input. uint4 I/O,
// packed (m,l) loads (one float2 per split instead of two scattered floats).
// ---------------------------------------------------------------------------
__global__ void combine_kernel()
{
    int idx = blockIdx.x * 256 + threadIdx.x;   // uint4 index over SEQ*DMODEL/8
    int row = idx >> 7;                          // 128 uint4-groups per row
    int h   = (idx & 127) >> 3;                  // 8 groups per head
    size_t mlb = (size_t)h * SEQ + row;
    float2 ml0 = g_pml[mlb];
    float2 ml1 = g_pml[(size_t)NH * SEQ + mlb];
    float ms = fmaxf(ml0.x, ml1.x);
    float w0 = ex2(ml0.x - ms), w1 = ex2(ml1.x - ms);
    float inv = 1.0f / (w0 * ml0.y + w1 * ml1.y);
    w0 *= inv; w1 *= inv;
    uint4 ua = ((const uint4*)g_opart)[idx];
    uint4 ub = ((const uint4*)(g_opart + (size_t)SEQ * DMODEL))[idx];
    uint4 uo;
    __half2* pa = (__half2*)&ua;
    __half2* pb = (__half2*)&ub;
    __half2* po = (__half2*)&uo;
#pragma unroll
    for (int q = 0; q < 4; q++) {
        float2 fa = __half22float2(pa[q]);
        float2 fb = __half22float2(pb[q]);
        po[q] = __floats2half2_rn(fa.x * w0 + fb.x * w1, fa.y * w0 + fb.y * w1);
    }
    ((uint4*)g_x16)[idx] = uo;
}

// ---------------------------------------------------------------------------
extern "C" void kernel_launch(void* const* d_in, const int* in_sizes, int n_in,
                              void* d_out, int out_size)
{
    const float* X     = (const float*)d_in[0];
    const float* Wqkv  = (const float*)d_in[1];
    const float* bqkv  = (const float*)d_in[2];
    const float* Wproj = (const float*)d_in[3];
    const float* bproj = (const float*)d_in[4];
    float* out = (float*)d_out;

    const int GEMM_SMEM = 3 * 2 * 16384;             // 98304 B, 2 CTAs/SM
    const int ATTN_SMEM = 16384 + 4 * 16384;         // 81920 B, 2 CTAs/SM
    cudaFuncSetAttribute(gemm16<1>, cudaFuncAttributeMaxDynamicSharedMemorySize, GEMM_SMEM);
    cudaFuncSetAttribute(gemm16<0>, cudaFuncAttributeMaxDynamicSharedMemorySize, GEMM_SMEM);
    cudaFuncSetAttribute(attn_mma_kernel, cudaFuncAttributeMaxDynamicSharedMemorySize, ATTN_SMEM);

    // 1) fused operand conversion
    conv_all_kernel<<<8192, 256>>>(X, Wqkv, Wproj);

    // 2) QKV GEMM -> fp16 q(scaled)/k/v
    gemm16<1><<<dim3(24, 32), 128, GEMM_SMEM>>>(bqkv, nullptr, 3 * DMODEL);

    // 3) split-KV attention (heavy q-blocks first globally) + combine -> g_x16
    attn_mma_kernel<<<dim3(KSPLIT, NH, 32), 128, ATTN_SMEM>>>();
    combine_kernel<<<SEQ * DMODEL / 8 / 256, 256>>>();

    // 4) proj GEMM -> out
    gemm16<0><<<dim3(8, 32), 128, GEMM_SMEM>>>(bproj, out, DMODEL);
}

// round 17
// speedup vs baseline: 1.2226x; 1.0268x over previous
#include <cuda_runtime.h>
#include <cuda_fp16.h>
#include <cstdint>

#define SEQ  4096
#define DMODEL 1024
#define NH   16
#define HDIM 64
#define KSPLIT 2

// single fp16 A operand: X for QKV GEMM, then combined attention output for proj
__device__ __align__(16) __half g_x16[(long)SEQ * DMODEL];
// single fp16 weights, SAME layout as input: [K][N] (consumed k-major via ldsm.trans)
__device__ __align__(16) __half g_w1[(long)DMODEL * 3 * DMODEL];
__device__ __align__(16) __half g_w2[(long)DMODEL * DMODEL];
// fp16 q/k/v (q pre-scaled by 0.125*log2e), head-major [h][seq][hd]
__device__ __align__(16) __half g_q16[(long)NH * SEQ * HDIM];
__device__ __align__(16) __half g_k16[(long)NH * SEQ * HDIM];
__device__ __align__(16) __half g_v16[(long)NH * SEQ * HDIM];
// split-KV partials: unnormalized O (fp16) + per-row packed (m,l) (fp32 exp2 domain)
__device__ __align__(16) __half g_opart[(long)KSPLIT * SEQ * DMODEL];
__device__ __align__(8) float2 g_pml[(long)KSPLIT * NH * SEQ];

#define QSCALE 0.18033688f   // 0.125 * log2(e)

// ---------------------------------------------------------------------------
__device__ __forceinline__ uint32_t smem_u32(const void* p) {
    uint32_t a;
    asm("{ .reg .u64 t; cvta.to.shared.u64 t, %1; cvt.u32.u64 %0, t; }" : "=r"(a) : "l"(p));
    return a;
}
__device__ __forceinline__ float ex2(float x) {
    float y; asm("ex2.approx.f32 %0, %1;" : "=f"(y) : "f"(x)); return y;
}
__device__ __forceinline__ uint32_t ex2h2(uint32_t x) {
    uint32_t y; asm("ex2.approx.f16x2 %0, %1;" : "=r"(y) : "r"(x)); return y;
}
#define CP16(dst, src) \
    asm volatile("cp.async.cg.shared.global [%0], [%1], 16;" :: "r"(dst), "l"(src))
#define CP_COMMIT() asm volatile("cp.async.commit_group;" ::: "memory")
#define CP_WAIT2()  asm volatile("cp.async.wait_group 2;" ::: "memory")
#define CP_WAIT1()  asm volatile("cp.async.wait_group 1;" ::: "memory")
#define CP_WAIT0()  asm volatile("cp.async.wait_group 0;" ::: "memory")

#define LDSM4(r0, r1, r2, r3, addr) \
    asm volatile("ldmatrix.sync.aligned.m8n8.x4.shared.b16 {%0,%1,%2,%3}, [%4];" \
                 : "=r"(r0), "=r"(r1), "=r"(r2), "=r"(r3) : "r"(addr))
#define LDSM4T(r0, r1, r2, r3, addr) \
    asm volatile("ldmatrix.sync.aligned.m8n8.x4.trans.shared.b16 {%0,%1,%2,%3}, [%4];" \
                 : "=r"(r0), "=r"(r1), "=r"(r2), "=r"(r3) : "r"(addr))

#define MMAH(c, a, b0, b1) \
    asm volatile("mma.sync.aligned.m16n8k16.row.col.f32.f16.f16.f32 " \
                 "{%0,%1,%2,%3}, {%4,%5,%6,%7}, {%8,%9}, {%0,%1,%2,%3};" \
                 : "+f"((c)[0]), "+f"((c)[1]), "+f"((c)[2]), "+f"((c)[3]) \
                 : "r"((a)[0]), "r"((a)[1]), "r"((a)[2]), "r"((a)[3]), \
                   "r"(b0), "r"(b1))

__device__ __forceinline__ uint32_t h2u(__half2 h) { return *(uint32_t*)&h; }

// ---------------------------------------------------------------------------
// Fused conversion kernel, 2 float4 per thread: X, Wqkv, Wproj -> fp16.
// Block ranges (512 float4s per block): X 2048, W1 1536, W2 512 blocks.
// ---------------------------------------------------------------------------
__global__ void conv_all_kernel(const float* __restrict__ X,
                                const float* __restrict__ W1,
                                const float* __restrict__ W2) {
    int b = blockIdx.x;
    const float* src;
    __half* dst;
    int j0;   // first float4 index within the selected array
    if (b < 2048)      { src = X;  dst = g_x16; j0 = b * 512 + threadIdx.x; }
    else if (b < 3584) { src = W1; dst = g_w1;  j0 = (b - 2048) * 512 + threadIdx.x; }
    else               { src = W2; dst = g_w2;  j0 = (b - 3584) * 512 + threadIdx.x; }
#pragma unroll
    for (int r = 0; r < 2; r++) {
        int j = j0 + r * 256;
        float4 v = ((const float4*)src)[j];
        __half2* H = (__half2*)dst;
        H[2*j]   = __floats2half2_rn(v.x, v.y);
        H[2*j+1] = __floats2half2_rn(v.z, v.w);
    }
}

// ---------------------------------------------------------------------------
// Single-fp16 GEMM, 128 threads / 4 warps, warp tile 64x64 (round-12 config).
// ---------------------------------------------------------------------------
template <int MODE>
__global__ __launch_bounds__(128, 2) void gemm16(
    const float* __restrict__ bias, float* __restrict__ C, int N)
{
    const __half* __restrict__ B = MODE ? g_w1 : g_w2;
    const int K = DMODEL;
    extern __shared__ char smem[];
    const uint32_t sb = smem_u32(smem);
    const int tid  = threadIdx.x;
    const int lane = tid & 31;
    const int wid  = tid >> 5;
    const int wm   = wid >> 1;
    const int wn   = wid & 1;
    const int n0 = blockIdx.x * 128, m0 = blockIdx.y * 128;

    float acc[4][8][4];
#pragma unroll
    for (int mt = 0; mt < 4; mt++)
#pragma unroll
        for (int nt = 0; nt < 8; nt++)
#pragma unroll
            for (int r = 0; r < 4; r++) acc[mt][nt][r] = 0.f;

    auto load_stage = [&](int stg, int ck) {
        const uint32_t st = sb + (uint32_t)stg * 32768;
        const int k0 = ck * 64;
#pragma unroll
        for (int it = 0; it < 8; it++) {
            int id  = it * 128 + tid;
            int row = id >> 3, kc = id & 7;
            const void* g = g_x16 + (size_t)(m0 + row) * K + k0 + kc * 8;
            uint32_t soff = (uint32_t)(row * 128 + ((kc * 16) ^ ((row & 7) << 4)));
            CP16(st + soff, g);
        }
#pragma unroll
        for (int it = 0; it < 8; it++) {
            int id  = it * 128 + tid;
            int row = id >> 4, c16 = id & 15;
            const void* g = B + (size_t)(k0 + row) * N + n0 + c16 * 8;
            uint32_t soff = (uint32_t)(row * 256 + ((c16 * 16) ^ ((row & 15) << 4)));
            CP16(st + 16384 + soff, g);
        }
    };

    const int NC = K / 64;
    load_stage(0, 0); CP_COMMIT();
    load_stage(1, 1); CP_COMMIT();

    const int r_lane = lane & 15;
    const int c_lane = (lane >> 4) << 4;
    const uint32_t xorA = (uint32_t)((r_lane & 7) << 4);
    const uint32_t xorB = (uint32_t)(r_lane << 4);
    const uint32_t colB = (uint32_t)(wn * 128 + c_lane);

    for (int c = 0; c < NC; c++) {
        if (c + 1 < NC) { CP_WAIT1(); } else { CP_WAIT0(); }
        __syncthreads();
        if (c + 2 < NC) { load_stage((c + 2) % 3, c + 2); CP_COMMIT(); }

        const uint32_t st = sb + (uint32_t)(c % 3) * 32768;
        const uint32_t aA = st +         (uint32_t)((wm * 64 + r_lane) * 128);
        const uint32_t rB = st + 16384 + (uint32_t)(r_lane * 256);

#pragma unroll
        for (int ks = 0; ks < 4; ks++) {
            const uint32_t cvA = ((uint32_t)(ks * 32 + c_lane)) ^ xorA;
            uint32_t ah[4][4], bh[4][4];
#pragma unroll
            for (int mt = 0; mt < 4; mt++)
                LDSM4(ah[mt][0], ah[mt][1], ah[mt][2], ah[mt][3], aA + mt * 2048 + cvA);
#pragma unroll
            for (int bn = 0; bn < 4; bn++)
                LDSM4T(bh[bn][0], bh[bn][1], bh[bn][2], bh[bn][3],
                       rB + ks * 4096 + ((colB + bn * 32) ^ xorB));
#pragma unroll
            for (int mt = 0; mt < 4; mt++)
#pragma unroll
                for (int nt = 0; nt < 8; nt++) {
                    int bn = nt >> 1, sub = nt & 1;
                    MMAH(acc[mt][nt], ah[mt], bh[bn][sub * 2], bh[bn][sub * 2 + 1]);
                }
        }
    }

    const int rq = lane >> 2;
    const int cq = (lane & 3) * 2;
#pragma unroll
    for (int mt = 0; mt < 4; mt++) {
#pragma unroll
        for (int nt = 0; nt < 8; nt++) {
            int gcol = n0 + wn * 64 + nt * 8 + cq;
            float b0 = bias[gcol], b1 = bias[gcol + 1];
            if (MODE == 1) {
                int sect = gcol >> 10, w = gcol & 1023;
                int hh = w >> 6, dd = w & 63;
                __half* dst = (sect == 0) ? g_q16 : (sect == 1) ? g_k16 : g_v16;
                float sc = (sect == 0) ? QSCALE : 1.0f;
#pragma unroll
                for (int half = 0; half < 2; half++) {
                    int grow = m0 + wm * 64 + mt * 16 + rq + half * 8;
                    float vx = (acc[mt][nt][half * 2 + 0] + b0) * sc;
                    float vy = (acc[mt][nt][half * 2 + 1] + b1) * sc;
                    *(__half2*)&dst[((size_t)hh * SEQ + grow) * HDIM + dd] =
                        __floats2half2_rn(vx, vy);
                }
            } else {
#pragma unroll
                for (int half = 0; half < 2; half++) {
                    int grow = m0 + wm * 64 + mt * 16 + rq + half * 8;
                    float2 v;
                    v.x = acc[mt][nt][half * 2 + 0] + b0;
                    v.y = acc[mt][nt][half * 2 + 1] + b1;
                    *(float2*)&C[(size_t)grow * N + gcol] = v;
                }
            }
        }
    }
}

// ---------------------------------------------------------------------------
// FlashAttention-2, split-KV x2, 4 warps x 32 rows, fp16 partials.
// Grid (KSPLIT, NH, 32), heavy q-blocks first globally (LPT).
// Softmax exponentials in fp16x2 (halved MUFU); P emerges directly as fp16
// MMA fragments. Row sums kept in fp32. 4-stage KV pipeline, 2 CTAs/SM.
// ---------------------------------------------------------------------------
__global__ __launch_bounds__(128, 2) void attn_mma_kernel()
{
    extern __shared__ char smem[];
    const uint32_t sb = smem_u32(smem);
    const int tid = threadIdx.x, lane = tid & 31, wid = tid >> 5;
    const int sp = blockIdx.x;
    const int h  = blockIdx.y;
    const int iq = 31 - (int)blockIdx.z;     // heavy blocks first, globally
    const int jbeg = sp * (iq + 1);
    const int jend = jbeg + iq + 1;

    const uint32_t Qs = sb;                  // 16KB

    auto load_kv = [&](int stg, int j) {
        const uint32_t st = sb + 16384 + (uint32_t)stg * 16384;
#pragma unroll
        for (int a = 0; a < 2; a++) {
            const __half* src = a ? g_v16 : g_k16;
#pragma unroll
            for (int it = 0; it < 4; it++) {
                int id = it * 128 + tid;
                int row = id >> 3, kc = id & 7;
                uint32_t soff = (uint32_t)(row * 128 + ((kc * 16) ^ ((row & 7) << 4)));
                CP16(st + a * 8192 + soff,
                     src + ((size_t)h * SEQ + j * 64 + row) * HDIM + kc * 8);
            }
        }
    };

    {
#pragma unroll
        for (int it = 0; it < 8; it++) {
            int id = it * 128 + tid;
            int row = id >> 3, kc = id & 7;
            uint32_t soff = (uint32_t)(row * 128 + ((kc * 16) ^ ((row & 7) << 4)));
            CP16(Qs + soff, g_q16 + ((size_t)h * SEQ + iq * 128 + row) * HDIM + kc * 8);
        }
        load_kv(0, jbeg);
        CP_COMMIT();
        if (jbeg + 1 < jend) { load_kv(1, jbeg + 1); CP_COMMIT(); }
        if (jbeg + 2 < jend) { load_kv(2, jbeg + 2); CP_COMMIT(); }
    }

    float o[2][8][4];
#pragma unroll
    for (int mt = 0; mt < 2; mt++)
#pragma unroll
        for (int nt = 0; nt < 8; nt++)
#pragma unroll
            for (int r = 0; r < 4; r++) o[mt][nt][r] = 0.f;
    float mst[2][2], lst[2][2];
#pragma unroll
    for (int mt = 0; mt < 2; mt++) { mst[mt][0] = mst[mt][1] = -1e30f;
                                     lst[mt][0] = lst[mt][1] = 0.f; }
    uint32_t qf[2][4][4];

    const uint32_t xorterm = (uint32_t)((lane & 7) << 4);
    const uint32_t c_lane  = (uint32_t)((lane >> 4) << 4);
    int r0g[2];
#pragma unroll
    for (int mt = 0; mt < 2; mt++)
        r0g[mt] = iq * 128 + wid * 32 + mt * 16 + (lane >> 2);

    for (int j = jbeg; j < jend; j++) {
        const int jj = j - jbeg;
        if (j + 2 < jend)      { CP_WAIT2(); }
        else if (j + 1 < jend) { CP_WAIT1(); }
        else                   { CP_WAIT0(); }
        __syncthreads();
        if (j + 3 < jend) { load_kv((jj + 3) & 3, j + 3); CP_COMMIT(); }

        if (jj == 0) {
#pragma unroll
            for (int mt = 0; mt < 2; mt++) {
                const uint32_t qrow = Qs +
                    (uint32_t)((wid * 32 + mt * 16 + (lane & 15)) * 128);
#pragma unroll
                for (int ks = 0; ks < 4; ks++) {
                    uint32_t cv = ((uint32_t)(ks * 32) + c_lane) ^ xorterm;
                    LDSM4(qf[mt][ks][0], qf[mt][ks][1], qf[mt][ks][2], qf[mt][ks][3],
                          qrow + cv);
                }
            }
        }

        const uint32_t st = sb + 16384 + (uint32_t)(jj & 3) * 16384;
        const uint32_t Ks = st, Vs = st + 8192;

        float s[2][8][4];
#pragma unroll
        for (int mt = 0; mt < 2; mt++)
#pragma unroll
            for (int nt = 0; nt < 8; nt++)
#pragma unroll
                for (int r = 0; r < 4; r++) s[mt][nt][r] = 0.f;

#pragma unroll
        for (int ks = 0; ks < 4; ks++) {
            uint32_t cv = ((uint32_t)(ks * 32) + c_lane) ^ xorterm;
#pragma unroll
            for (int bn = 0; bn < 4; bn++) {
                uint32_t kh[4];
                LDSM4(kh[0], kh[1], kh[2], kh[3],
                      Ks + (uint32_t)((bn * 16 + (lane & 15)) * 128) + cv);
#pragma unroll
                for (int mt = 0; mt < 2; mt++)
#pragma unroll
                    for (int sub = 0; sub < 2; sub++)
                        MMAH(s[mt][bn * 2 + sub], qf[mt][ks], kh[sub], kh[sub + 2]);
            }
        }

        if (j >= 2 * iq) {
            int cbase = j * 64 + (lane & 3) * 2;
#pragma unroll
            for (int mt = 0; mt < 2; mt++)
#pragma unroll
                for (int nt = 0; nt < 8; nt++) {
                    int c0 = cbase + nt * 8, c1 = c0 + 1;
                    if (c0 > r0g[mt])     s[mt][nt][0] = -1e30f;
                    if (c1 > r0g[mt])     s[mt][nt][1] = -1e30f;
                    if (c0 > r0g[mt] + 8) s[mt][nt][2] = -1e30f;
                    if (c1 > r0g[mt] + 8) s[mt][nt][3] = -1e30f;
                }
        }

        // ---- online softmax: exponentials in fp16x2, sums in fp32 ----
        uint32_t ph[2][8][2];   // P fragments (fp16x2), fed straight to PV MMA
#pragma unroll
        for (int mt = 0; mt < 2; mt++) {
            float mx0 = -1e30f, mx1 = -1e30f;
#pragma unroll
            for (int nt = 0; nt < 8; nt++) {
                mx0 = fmaxf(mx0, fmaxf(s[mt][nt][0], s[mt][nt][1]));
                mx1 = fmaxf(mx1, fmaxf(s[mt][nt][2], s[mt][nt][3]));
            }
            mx0 = fmaxf(mx0, __shfl_xor_sync(0xFFFFFFFFu, mx0, 1));
            mx0 = fmaxf(mx0, __shfl_xor_sync(0xFFFFFFFFu, mx0, 2));
            mx1 = fmaxf(mx1, __shfl_xor_sync(0xFFFFFFFFu, mx1, 1));
            mx1 = fmaxf(mx1, __shfl_xor_sync(0xFFFFFFFFu, mx1, 2));
            float mn0 = fmaxf(mst[mt][0], mx0), mn1 = fmaxf(mst[mt][1], mx1);
            float al0 = ex2(mst[mt][0] - mn0), al1 = ex2(mst[mt][1] - mn1);
            mst[mt][0] = mn0; mst[mt][1] = mn1;

            float sum0 = 0.f, sum1 = 0.f;
#pragma unroll
            for (int nt = 0; nt < 8; nt++) {
                __half2 d0 = __floats2half2_rn(s[mt][nt][0] - mn0, s[mt][nt][1] - mn0);
                __half2 d1 = __floats2half2_rn(s[mt][nt][2] - mn1, s[mt][nt][3] - mn1);
                uint32_t p0 = ex2h2(h2u(d0));
                uint32_t p1 = ex2h2(h2u(d1));
                ph[mt][nt][0] = p0;
                ph[mt][nt][1] = p1;
                float2 f0 = __half22float2(*(__half2*)&p0);
                float2 f1 = __half22float2(*(__half2*)&p1);
                sum0 += f0.x + f0.y;
                sum1 += f1.x + f1.y;
            }
            sum0 += __shfl_xor_sync(0xFFFFFFFFu, sum0, 1);
            sum0 += __shfl_xor_sync(0xFFFFFFFFu, sum0, 2);
            sum1 += __shfl_xor_sync(0xFFFFFFFFu, sum1, 1);
            sum1 += __shfl_xor_sync(0xFFFFFFFFu, sum1, 2);
            lst[mt][0] = lst[mt][0] * al0 + sum0;
            lst[mt][1] = lst[mt][1] * al1 + sum1;

#pragma unroll
            for (int nt = 0; nt < 8; nt++) {
                o[mt][nt][0] *= al0; o[mt][nt][1] *= al0;
                o[mt][nt][2] *= al1; o[mt][nt][3] *= al1;
            }
        }

        // ---- O += P @ V (P fragments already fp16) ----
#pragma unroll
        for (int t = 0; t < 4; t++) {
            uint32_t rowoff = (uint32_t)((t * 16 + (lane & 15)) * 128);
#pragma unroll
            for (int g = 0; g < 4; g++) {
                uint32_t cvv = ((uint32_t)(g * 32) + c_lane) ^ xorterm;
                uint32_t vh[4];
                LDSM4T(vh[0], vh[1], vh[2], vh[3], Vs + rowoff + cvv);
#pragma unroll
                for (int mt = 0; mt < 2; mt++) {
                    uint32_t ap[4] = { ph[mt][t * 2][0],     ph[mt][t * 2][1],
                                       ph[mt][t * 2 + 1][0], ph[mt][t * 2 + 1][1] };
                    MMAH(o[mt][g * 2],     ap, vh[0], vh[1]);
                    MMAH(o[mt][g * 2 + 1], ap, vh[2], vh[3]);
                }
            }
        }
    }

    // ---- write unnormalized partials (fp16) + packed (m,l) ----
    __half* Op = g_opart + (size_t)sp * SEQ * DMODEL;
    int colb = h * 64 + (lane & 3) * 2;
#pragma unroll
    for (int mt = 0; mt < 2; mt++) {
#pragma unroll
        for (int nt = 0; nt < 8; nt++) {
            int col = colb + nt * 8;
            size_t i0 = (size_t)r0g[mt] * DMODEL + col;
            size_t i1 = (size_t)(r0g[mt] + 8) * DMODEL + col;
            *(__half2*)&Op[i0] = __floats2half2_rn(o[mt][nt][0], o[mt][nt][1]);
            *(__half2*)&Op[i1] = __floats2half2_rn(o[mt][nt][2], o[mt][nt][3]);
        }
        if ((lane & 3) == 0) {
            size_t base = (size_t)sp * NH * SEQ + (size_t)h * SEQ;
            float2 a; a.x = mst[mt][0]; a.y = lst[mt][0];
            float2 b; b.x = mst[mt][1]; b.y = lst[mt][1];
            g_pml[base + r0g[mt]]     = a;
            g_pml[base + r0g[mt] + 8] = b;
        }
    }
}

// ---------------------------------------------------------------------------
// Combine split-KV partials (exp2 domain) -> fp16 proj input. 2 uint4 per
// thread (consecutive, same head/row), packed (m,l) loads.
// ---------------------------------------------------------------------------
__global__ void combine_kernel()
{
    int t = blockIdx.x * 256 + threadIdx.x;
    int base = t * 2;                            // uint4 index (pairs share head)
    int row = base >> 7;                         // 128 uint4-groups per row
    int h   = (base & 127) >> 3;                 // 8 groups per head
    size_t mlb = (size_t)h * SEQ + row;
    float2 ml0 = g_pml[mlb];
    float2 ml1 = g_pml[(size_t)NH * SEQ + mlb];
    float ms = fmaxf(ml0.x, ml1.x);
    float w0 = ex2(ml0.x - ms), w1 = ex2(ml1.x - ms);
    float inv = 1.0f / (w0 * ml0.y + w1 * ml1.y);
    w0 *= inv; w1 *= inv;
#pragma unroll
    for (int r = 0; r < 2; r++) {
        int idx = base + r;
        uint4 ua = ((const uint4*)g_opart)[idx];
        uint4 ub = ((const uint4*)(g_opart + (size_t)SEQ * DMODEL))[idx];
        uint4 uo;
        __half2* pa = (__half2*)&ua;
        __half2* pb = (__half2*)&ub;
        __half2* po = (__half2*)&uo;
#pragma unroll
        for (int q = 0; q < 4; q++) {
            float2 fa = __half22float2(pa[q]);
            float2 fb = __half22float2(pb[q]);
            po[q] = __floats2half2_rn(fa.x * w0 + fb.x * w1, fa.y * w0 + fb.y * w1);
        }
        ((uint4*)g_x16)[idx] = uo;
    }
}

// ---------------------------------------------------------------------------
extern "C" void kernel_launch(void* const* d_in, const int* in_sizes, int n_in,
                              void* d_out, int out_size)
{
    const float* X     = (const float*)d_in[0];
    const float* Wqkv  = (const float*)d_in[1];
    const float* bqkv  = (const float*)d_in[2];
    const float* Wproj = (const float*)d_in[3];
    const float* bproj = (const float*)d_in[4];
    float* out = (float*)d_out;

    const int GEMM_SMEM = 3 * 2 * 16384;             // 98304 B, 2 CTAs/SM
    const int ATTN_SMEM = 16384 + 4 * 16384;         // 81920 B, 2 CTAs/SM
    cudaFuncSetAttribute(gemm16<1>, cudaFuncAttributeMaxDynamicSharedMemorySize, GEMM_SMEM);
    cudaFuncSetAttribute(gemm16<0>, cudaFuncAttributeMaxDynamicSharedMemorySize, GEMM_SMEM);
    cudaFuncSetAttribute(attn_mma_kernel, cudaFuncAttributeMaxDynamicSharedMemorySize, ATTN_SMEM);

    // 1) fused operand conversion (2 float4 / thread)
    conv_all_kernel<<<4096, 256>>>(X, Wqkv, Wproj);

    // 2) QKV GEMM -> fp16 q(scaled)/k/v
    gemm16<1><<<dim3(24, 32), 128, GEMM_SMEM>>>(bqkv, nullptr, 3 * DMODEL);

    // 3) split-KV attention (fp16x2 softmax) + combine -> g_x16
    attn_mma_kernel<<<dim3(KSPLIT, NH, 32), 128, ATTN_SMEM>>>();
    combine_kernel<<<SEQ * DMODEL / 16 / 256, 256>>>();

    // 4) proj GEMM -> out
    gemm16<0><<<dim3(8, 32), 128, GEMM_SMEM>>>(bproj, out, DMODEL);
}